// round 7
// baseline (speedup 1.0000x reference)
#include <cuda_runtime.h>
#include <cstdint>

static constexpr int BATCH = 4;
static constexpr int SEQ   = 2048;
static constexpr int DIM   = 1024;

// Scratch (device globals: allocation-guard safe)
__device__ float g_x [BATCH * SEQ * DIM];   // tf32-rounded, K-permuted x
__device__ float g_wq[DIM * DIM];           // tf32-rounded, K-permuted weights
__device__ float g_wk[DIM * DIM];
__device__ float g_wv[DIM * DIM];
__device__ float g_q [BATCH * SEQ * DIM];   // rounded+permuted Q
__device__ float g_k [BATCH * SEQ * DIM];   // rounded+permuted K
__device__ float g_v [BATCH * SEQ * DIM];   // rounded V (plain layout)
__device__ float g_vt[BATCH * DIM * SEQ];   // V^T, rounded, s-permuted
__device__ float g_p [BATCH * SEQ * SEQ];   // rounded, t-permuted attn weights

// K-permutation within each 32-element block: pos(k) = (k%4)*8 + k/4.
// MMA fragment loads then read contiguous 16B runs. Always within a 128B line.
__device__ __forceinline__ int kperm(int idx) {
    return (idx & ~31) | (((idx & 3) << 3) | ((idx & 31) >> 2));
}

__device__ __forceinline__ float round_tf32(float x) {
    uint32_t u;
    asm("cvt.rna.tf32.f32 %0, %1;" : "=r"(u) : "f"(x));
    return __uint_as_float(u);
}

__device__ __forceinline__ void mma_tf32(float (&c)[4],
                                         float a0, float a1, float a2, float a3,
                                         float b0, float b1) {
    asm volatile(
        "mma.sync.aligned.m16n8k8.row.col.f32.tf32.tf32.f32 "
        "{%0,%1,%2,%3}, {%4,%5,%6,%7}, {%8,%9}, {%0,%1,%2,%3};\n"
        : "+f"(c[0]), "+f"(c[1]), "+f"(c[2]), "+f"(c[3])
        : "r"(__float_as_uint(a0)), "r"(__float_as_uint(a1)),
          "r"(__float_as_uint(a2)), "r"(__float_as_uint(a3)),
          "r"(__float_as_uint(b0)), "r"(__float_as_uint(b1)));
}

#define CPA16(dst, src) \
    asm volatile("cp.async.cg.shared.global [%0], [%1], 16;\n" :: "r"(dst), "l"(src))

// ---------------------------------------------------------------------------
// tf32 round + K-permute pass (reads float4; writes 4 scalars in same line)
// ---------------------------------------------------------------------------
__global__ __launch_bounds__(256)
void round_perm_kernel(const float* __restrict__ in, float* __restrict__ out, int n4)
{
    int i = blockIdx.x * 256 + threadIdx.x;
    if (i < n4) {
        float4 v = ((const float4*)in)[i];
        const int idx4 = i * 4;
        const int base = idx4 & ~31;
        const int sub  = (idx4 & 31) >> 2;
        out[base + sub +  0] = round_tf32(v.x);
        out[base + sub +  8] = round_tf32(v.y);
        out[base + sub + 16] = round_tf32(v.z);
        out[base + sub + 24] = round_tf32(v.w);
    }
}

// ---------------------------------------------------------------------------
// TF32 tensor-core GEMM on K-permuted operands:  C = alpha*(A @ B^T) + bias
//   A [M,K], B [N,K], both row-major with every 32-block of K permuted.
//   All fragment loads are LDS.128. 128x128 tile, BK=32, 8 warps (64x32),
//   double-buffered cp.async, 2 CTAs/SM.
//   PERM_OUT: store C with K-permuted columns (and tf32-rounded) for reuse
//             as the next GEMM's operand.
// ---------------------------------------------------------------------------
template <bool ROUND_OUT, bool PERM_OUT>
__global__ __launch_bounds__(256, 2)
void gemm_kp(const float* __restrict__ A, const float* __restrict__ B,
             const float* __restrict__ bias, float* __restrict__ C,
             int M, int N, int K, float alpha, long sA, long sB, long sC)
{
    constexpr int BM = 128, BN = 128, BK = 32;
    constexpr int AP = 36;                      // row pitch (floats), conflict-free
    constexpr int BS_OFF = 2 * BM * AP;

    extern __shared__ float smem[];
    float* As = smem;
    float* Bs = smem + BS_OFF;
    uint32_t sbase;
    asm("{ .reg .u64 t; cvta.to.shared.u64 t, %1; cvt.u32.u64 %0, t; }"
        : "=r"(sbase) : "l"(smem));

    const float* Ab = A + (long)blockIdx.z * sA;
    const float* Bb = B + (long)blockIdx.z * sB;
    float*       Cb = C + (long)blockIdx.z * sC;

    const int n0   = blockIdx.x * BN;
    const int m0   = blockIdx.y * BM;
    const int tid  = threadIdx.x;
    const int warp = tid >> 5;
    const int lane = tid & 31;
    const int g    = lane >> 2;
    const int tg   = lane & 3;
    const int wm   = (warp & 1) * 64;
    const int wn   = (warp >> 1) * 32;

    const int arow = tid >> 3;            // 0..31
    const int acol = (tid & 7) * 4;       // 0..28

    float acc[4][4][4];
    #pragma unroll
    for (int i = 0; i < 4; ++i)
        #pragma unroll
        for (int j = 0; j < 4; ++j)
            #pragma unroll
            for (int r = 0; r < 4; ++r) acc[i][j][r] = 0.0f;

    auto load_tile = [&](int kt, int buf) {
        const int k0 = kt * BK;
        #pragma unroll
        for (int i = 0; i < 4; ++i) {
            int r = arow + i * 32;
            uint32_t dst = sbase + (uint32_t)(((buf * BM + r) * AP + acol) * 4);
            CPA16(dst, Ab + (long)(m0 + r) * K + k0 + acol);
        }
        #pragma unroll
        for (int i = 0; i < 4; ++i) {
            int r = arow + i * 32;
            uint32_t dst = sbase + (uint32_t)((BS_OFF + (buf * BM + r) * AP + acol) * 4);
            CPA16(dst, Bb + (long)(n0 + r) * K + k0 + acol);
        }
        asm volatile("cp.async.commit_group;\n");
    };

    const int ntiles = K / BK;
    load_tile(0, 0);

    for (int kt = 0; kt < ntiles; ++kt) {
        const int buf = kt & 1;
        if (kt + 1 < ntiles) {
            load_tile(kt + 1, buf ^ 1);
            asm volatile("cp.async.wait_group 1;\n");
        } else {
            asm volatile("cp.async.wait_group 0;\n");
        }
        __syncthreads();

        // Permuted layout: position tg*8 + {2kk, 2kk+1} holds k = 8kk+tg, 8kk+tg+4.
        // One LDS.128 covers 2 consecutive k-steps for this thread.
        #pragma unroll
        for (int half = 0; half < 2; ++half) {
            const int off = tg * 8 + half * 4;
            float4 bfv[4];
            #pragma unroll
            for (int ni = 0; ni < 4; ++ni)
                bfv[ni] = *(const float4*)&Bs[(buf * BM + wn + ni * 8 + g) * AP + off];
            #pragma unroll
            for (int mi = 0; mi < 4; ++mi) {
                const float* ap = &As[(buf * BM + wm + mi * 16 + g) * AP + off];
                float4 ag = *(const float4*)ap;            // row g
                float4 ah = *(const float4*)(ap + 8 * AP); // row g+8
                #pragma unroll
                for (int ni = 0; ni < 4; ++ni)
                    mma_tf32(acc[mi][ni], ag.x, ah.x, ag.y, ah.y,
                             bfv[ni].x, bfv[ni].y);        // kk = 2*half
                #pragma unroll
                for (int ni = 0; ni < 4; ++ni)
                    mma_tf32(acc[mi][ni], ag.z, ah.z, ag.w, ah.w,
                             bfv[ni].z, bfv[ni].w);        // kk = 2*half+1
            }
        }
        __syncthreads();
    }

    // Epilogue
    #pragma unroll
    for (int mi = 0; mi < 4; ++mi) {
        const int row = m0 + wm + mi * 16 + g;
        #pragma unroll
        for (int ni = 0; ni < 4; ++ni) {
            const int col = n0 + wn + ni * 8 + tg * 2;
            float vals[4] = {acc[mi][ni][0] * alpha, acc[mi][ni][1] * alpha,
                             acc[mi][ni][2] * alpha, acc[mi][ni][3] * alpha};
            if (bias) {
                float2 b = *(const float2*)&bias[col];
                vals[0] += b.x; vals[1] += b.y; vals[2] += b.x; vals[3] += b.y;
            }
            if (ROUND_OUT) {
                #pragma unroll
                for (int r = 0; r < 4; ++r) vals[r] = round_tf32(vals[r]);
            }
            if (PERM_OUT) {
                const int c0 = kperm(col), c1 = kperm(col + 1);
                Cb[(long)row * N + c0]       = vals[0];
                Cb[(long)row * N + c1]       = vals[1];
                Cb[(long)(row + 8) * N + c0] = vals[2];
                Cb[(long)(row + 8) * N + c1] = vals[3];
            } else {
                *(float2*)&Cb[(long)row * N + col]       = make_float2(vals[0], vals[1]);
                *(float2*)&Cb[(long)(row + 8) * N + col] = make_float2(vals[2], vals[3]);
            }
        }
    }
}

// ---------------------------------------------------------------------------
// V transpose [B][S][D] -> [B][D][S], tf32-rounded, s-permuted output columns
// ---------------------------------------------------------------------------
__global__ __launch_bounds__(256)
void transpose_vp(const float* __restrict__ in, float* __restrict__ out)
{
    __shared__ float t[32][33];
    const float* ib = in  + (long)blockIdx.z * SEQ * DIM;
    float*       ob = out + (long)blockIdx.z * DIM * SEQ;
    const int d0 = blockIdx.x * 32;
    const int s0 = blockIdx.y * 32;
    const int tx = threadIdx.x;       // 0..31
    const int ty = threadIdx.y;       // 0..7
    #pragma unroll
    for (int j = 0; j < 32; j += 8)
        t[ty + j][tx] = ib[(long)(s0 + ty + j) * DIM + d0 + tx];
    __syncthreads();
    const int sp = s0 + (((tx & 3) << 3) | (tx >> 2));   // permuted s index
    #pragma unroll
    for (int j = 0; j < 32; j += 8)
        ob[(long)(d0 + ty + j) * SEQ + sp] = round_tf32(t[tx][ty + j]);
}

// ---------------------------------------------------------------------------
// In-place row softmax (exact -> data) + rounded, t-permuted copy -> rounded
// ---------------------------------------------------------------------------
__global__ __launch_bounds__(256)
void softmax_kernel(float* __restrict__ data, float* __restrict__ rounded)
{
    constexpr int NC = SEQ;
    constexpr int PT = NC / 256;

    const long roff = (long)blockIdx.x * NC;
    float* row = data + roff;
    float* rr  = rounded + roff;
    __shared__ float red[8];

    const int tid  = threadIdx.x;
    const int lane = tid & 31;
    const int warp = tid >> 5;

    float v[PT];
    #pragma unroll
    for (int i = 0; i < PT; ++i) v[i] = row[tid + i * 256];

    float lmax = v[0];
    #pragma unroll
    for (int i = 1; i < PT; ++i) lmax = fmaxf(lmax, v[i]);
    #pragma unroll
    for (int o = 16; o > 0; o >>= 1)
        lmax = fmaxf(lmax, __shfl_xor_sync(0xFFFFFFFFu, lmax, o));
    if (lane == 0) red[warp] = lmax;
    __syncthreads();
    float rmax = red[0];
    #pragma unroll
    for (int w = 1; w < 8; ++w) rmax = fmaxf(rmax, red[w]);
    __syncthreads();

    float lsum = 0.0f;
    #pragma unroll
    for (int i = 0; i < PT; ++i) {
        v[i] = __expf(v[i] - rmax);
        lsum += v[i];
    }
    #pragma unroll
    for (int o = 16; o > 0; o >>= 1)
        lsum += __shfl_xor_sync(0xFFFFFFFFu, lsum, o);
    if (lane == 0) red[warp] = lsum;
    __syncthreads();
    float rsum = 0.0f;
    #pragma unroll
    for (int w = 0; w < 8; ++w) rsum += red[w];

    const float inv = 1.0f / rsum;
    #pragma unroll
    for (int i = 0; i < PT; ++i) {
        const int idx = tid + i * 256;
        const float o = v[i] * inv;
        row[idx] = o;
        rr[kperm(idx)] = round_tf32(o);
    }
}

// ---------------------------------------------------------------------------
// Launch: round+perm(x,W) -> QKV proj -> V^T -> scores -> softmax -> AV
// Output layout: [weighted_sum B*S*D | attention_weights B*S*S]
// ---------------------------------------------------------------------------
extern "C" void kernel_launch(void* const* d_in, const int* in_sizes, int n_in,
                              void* d_out, int out_size)
{
    const float* x  = (const float*)d_in[0];
    const float* Wq = (const float*)d_in[1];
    const float* bq = (const float*)d_in[2];
    const float* Wk = (const float*)d_in[3];
    const float* bk = (const float*)d_in[4];
    const float* Wv = (const float*)d_in[5];
    const float* bv = (const float*)d_in[6];

    float* out_ws = (float*)d_out;
    float* out_aw = (float*)d_out + (long)BATCH * SEQ * DIM;

    float *xr, *wq, *wk, *wv, *q, *k, *v, *vt, *p;
    cudaGetSymbolAddress((void**)&xr, g_x);
    cudaGetSymbolAddress((void**)&wq, g_wq);
    cudaGetSymbolAddress((void**)&wk, g_wk);
    cudaGetSymbolAddress((void**)&wv, g_wv);
    cudaGetSymbolAddress((void**)&q,  g_q);
    cudaGetSymbolAddress((void**)&k,  g_k);
    cudaGetSymbolAddress((void**)&v,  g_v);
    cudaGetSymbolAddress((void**)&vt, g_vt);
    cudaGetSymbolAddress((void**)&p,  g_p);

    const int smem_sz = 2 * (128 * 36 + 128 * 36) * 4;   // 73728
    cudaFuncSetAttribute(gemm_kp<true,  true >, cudaFuncAttributeMaxDynamicSharedMemorySize, smem_sz);
    cudaFuncSetAttribute(gemm_kp<false, false>, cudaFuncAttributeMaxDynamicSharedMemorySize, smem_sz);

    const dim3 blk(256);

    // 0) round to tf32 + K-permute inputs
    {
        const int nx = BATCH * SEQ * DIM / 4;
        const int nw = DIM * DIM / 4;
        round_perm_kernel<<<(nx + 255) / 256, blk>>>(x,  xr, nx);
        round_perm_kernel<<<(nw + 255) / 256, blk>>>(Wq, wq, nw);
        round_perm_kernel<<<(nw + 255) / 256, blk>>>(Wk, wk, nw);
        round_perm_kernel<<<(nw + 255) / 256, blk>>>(Wv, wv, nw);
    }

    // 1) QKV projections: Q,K rounded+permuted; V plain (transpose rounds it)
    {
        dim3 grid(DIM / 128, (BATCH * SEQ) / 128, 1);
        gemm_kp<true,  true ><<<grid, blk, smem_sz>>>(xr, wq, bq, q,
                                                      BATCH * SEQ, DIM, DIM, 1.0f, 0, 0, 0);
        gemm_kp<true,  true ><<<grid, blk, smem_sz>>>(xr, wk, bk, k,
                                                      BATCH * SEQ, DIM, DIM, 1.0f, 0, 0, 0);
        gemm_kp<false, false><<<grid, blk, smem_sz>>>(xr, wv, bv, v,
                                                      BATCH * SEQ, DIM, DIM, 1.0f, 0, 0, 0);
    }

    // 2) V^T: [S,D] -> [D,S], rounded + s-permuted
    {
        dim3 tgrid(DIM / 32, SEQ / 32, BATCH);
        transpose_vp<<<tgrid, dim3(32, 8)>>>(v, vt);
    }

    // 3) scores = (Q @ K^T) / 32, plain fp32 store into attn-weight region
    {
        dim3 grid(SEQ / 128, SEQ / 128, BATCH);
        gemm_kp<false, false><<<grid, blk, smem_sz>>>(q, k, nullptr, out_aw,
                                                      SEQ, SEQ, DIM, 0.03125f,
                                                      (long)SEQ * DIM, (long)SEQ * DIM,
                                                      (long)SEQ * SEQ);
    }

    // 4) softmax: exact -> out_aw, rounded+permuted -> p
    softmax_kernel<<<BATCH * SEQ, blk>>>(out_aw, p);

    // 5) weighted_sum = P @ Vt^T   (Vt: [D,S] row-major = B[N=D, K=S])
    {
        dim3 grid(DIM / 128, SEQ / 128, BATCH);
        gemm_kp<false, false><<<grid, blk, smem_sz>>>(p, vt, nullptr, out_ws,
                                                      SEQ, DIM, SEQ, 1.0f,
                                                      (long)SEQ * SEQ, (long)DIM * SEQ,
                                                      (long)SEQ * DIM);
    }
}

// round 8
// speedup vs baseline: 1.6553x; 1.6553x over previous
#include <cuda_runtime.h>
#include <cuda_fp16.h>
#include <cstdint>

static constexpr int BATCH = 4;
static constexpr int SEQ   = 2048;
static constexpr int DIM   = 1024;

// Scratch (device globals: allocation-guard safe), all fp16 operands
__device__ __half g_x [BATCH * SEQ * DIM];
__device__ __half g_wq[DIM * DIM];
__device__ __half g_wk[DIM * DIM];
__device__ __half g_wv[DIM * DIM];
__device__ __half g_q [BATCH * SEQ * DIM];
__device__ __half g_k [BATCH * SEQ * DIM];
__device__ __half g_v [BATCH * SEQ * DIM];
__device__ __half g_vt[BATCH * DIM * SEQ];   // V^T: [B][D][S]
__device__ __half g_p [BATCH * SEQ * SEQ];   // fp16 attention weights

// ---------------------------------------------------------------------------
__device__ __forceinline__ void mma_f16(float (&c)[4],
                                        uint32_t a0, uint32_t a1,
                                        uint32_t a2, uint32_t a3,
                                        uint32_t b0, uint32_t b1) {
    asm volatile(
        "mma.sync.aligned.m16n8k16.row.col.f32.f16.f16.f32 "
        "{%0,%1,%2,%3}, {%4,%5,%6,%7}, {%8,%9}, {%0,%1,%2,%3};\n"
        : "+f"(c[0]), "+f"(c[1]), "+f"(c[2]), "+f"(c[3])
        : "r"(a0), "r"(a1), "r"(a2), "r"(a3), "r"(b0), "r"(b1));
}

#define CPA16(dst, src) \
    asm volatile("cp.async.cg.shared.global [%0], [%1], 16;\n" :: "r"(dst), "l"(src))

// ---------------------------------------------------------------------------
// fp32 -> fp16 conversion pass (float4 in, 4 halves out)
// ---------------------------------------------------------------------------
__global__ __launch_bounds__(256)
void cvt_half_kernel(const float* __restrict__ in, __half* __restrict__ out, int n4)
{
    int i = blockIdx.x * 256 + threadIdx.x;
    if (i < n4) {
        float4 v = ((const float4*)in)[i];
        __half2 h01 = __floats2half2_rn(v.x, v.y);
        __half2 h23 = __floats2half2_rn(v.z, v.w);
        uint2 pk;
        pk.x = *(uint32_t*)&h01;
        pk.y = *(uint32_t*)&h23;
        ((uint2*)out)[i] = pk;
    }
}

// ---------------------------------------------------------------------------
// FP16 tensor-core GEMM (fp32 accum):  C = alpha * (A @ B^T) + bias
//   A [M,K], B [N,K], both row-major fp16. Batched via blockIdx.z strides.
// 128x128 block tile, BK=32, 256 threads (8 warps, 64x32 warp tiles),
// double-buffered cp.async, mma.m16n8k16, 2 CTAs/SM.
//   HALF_OUT: store C as fp16 (for operand reuse); else fp32.
// ---------------------------------------------------------------------------
template <bool HALF_OUT>
__global__ __launch_bounds__(256, 2)
void gemm_h(const __half* __restrict__ A, const __half* __restrict__ B,
            const float* __restrict__ bias, void* __restrict__ C,
            int M, int N, int K, float alpha, long sA, long sB, long sC)
{
    constexpr int BM = 128, BK = 32;
    constexpr int PH = 40;                     // row pitch in halves (80B)
    constexpr int TILE_H = BM * PH;            // halves per tile buffer
    constexpr int BS_OFF = 2 * TILE_H;         // Bs offset (halves)

    extern __shared__ __half smh[];
    __half* As = smh;
    __half* Bs = smh + BS_OFF;
    uint32_t sbase;
    asm("{ .reg .u64 t; cvta.to.shared.u64 t, %1; cvt.u32.u64 %0, t; }"
        : "=r"(sbase) : "l"(smh));

    const __half* Ab = A + (long)blockIdx.z * sA;
    const __half* Bb = B + (long)blockIdx.z * sB;

    const int n0   = blockIdx.x * 128;
    const int m0   = blockIdx.y * BM;
    const int tid  = threadIdx.x;
    const int warp = tid >> 5;
    const int lane = tid & 31;
    const int g    = lane >> 2;
    const int tg   = lane & 3;
    const int wm   = (warp & 1) * 64;
    const int wn   = (warp >> 1) * 32;

    // cp.async indices: 128 rows x 4 chunks of 16B per tile, 2 per thread
    const int cr = tid >> 1;                  // 0..127 row
    const int cc = (tid & 1) * 2;             // chunk 0/2 (+1 below)

    float acc[4][4][4];
    #pragma unroll
    for (int i = 0; i < 4; ++i)
        #pragma unroll
        for (int j = 0; j < 4; ++j)
            #pragma unroll
            for (int r = 0; r < 4; ++r) acc[i][j][r] = 0.0f;

    auto load_tile = [&](int kt, int buf) {
        const int k0 = kt * BK;
        {
            uint32_t dst = sbase + (uint32_t)((buf * TILE_H + cr * PH) * 2 + cc * 16);
            const __half* src = Ab + (long)(m0 + cr) * K + k0 + cc * 8;
            CPA16(dst, src);
            CPA16(dst + 16, src + 8);
        }
        {
            uint32_t dst = sbase + (uint32_t)((BS_OFF + buf * TILE_H + cr * PH) * 2 + cc * 16);
            const __half* src = Bb + (long)(n0 + cr) * K + k0 + cc * 8;
            CPA16(dst, src);
            CPA16(dst + 16, src + 8);
        }
        asm volatile("cp.async.commit_group;\n");
    };

    const int ntiles = K / BK;
    load_tile(0, 0);

    for (int kt = 0; kt < ntiles; ++kt) {
        const int buf = kt & 1;
        if (kt + 1 < ntiles) {
            load_tile(kt + 1, buf ^ 1);
            asm volatile("cp.async.wait_group 1;\n");
        } else {
            asm volatile("cp.async.wait_group 0;\n");
        }
        __syncthreads();

        #pragma unroll
        for (int kk = 0; kk < 2; ++kk) {       // 2 x K=16 per BK=32
            const int ko = kk * 16;
            uint32_t af[4][4];
            #pragma unroll
            for (int mi = 0; mi < 4; ++mi) {
                const __half* ap = &As[(buf * BM + wm + mi * 16 + g) * PH + ko + 2 * tg];
                af[mi][0] = *(const uint32_t*)ap;              // A[g][k..k+1]
                af[mi][1] = *(const uint32_t*)(ap + 8 * PH);   // A[g+8][k..k+1]
                af[mi][2] = *(const uint32_t*)(ap + 8);        // A[g][k+8..k+9]
                af[mi][3] = *(const uint32_t*)(ap + 8 * PH + 8);
            }
            uint32_t bf[4][2];
            #pragma unroll
            for (int ni = 0; ni < 4; ++ni) {
                const __half* bp = &Bs[(buf * BM + wn + ni * 8 + g) * PH + ko + 2 * tg];
                bf[ni][0] = *(const uint32_t*)bp;              // B^T[n][k..k+1]
                bf[ni][1] = *(const uint32_t*)(bp + 8);        // B^T[n][k+8..k+9]
            }
            #pragma unroll
            for (int mi = 0; mi < 4; ++mi)
                #pragma unroll
                for (int ni = 0; ni < 4; ++ni)
                    mma_f16(acc[mi][ni], af[mi][0], af[mi][1], af[mi][2],
                            af[mi][3], bf[ni][0], bf[ni][1]);
        }
        __syncthreads();
    }

    // Epilogue
    #pragma unroll
    for (int mi = 0; mi < 4; ++mi) {
        const int row = m0 + wm + mi * 16 + g;
        #pragma unroll
        for (int ni = 0; ni < 4; ++ni) {
            const int col = n0 + wn + ni * 8 + tg * 2;
            float v0 = acc[mi][ni][0] * alpha, v1 = acc[mi][ni][1] * alpha;
            float v2 = acc[mi][ni][2] * alpha, v3 = acc[mi][ni][3] * alpha;
            if (bias) {
                float2 b = *(const float2*)&bias[col];
                v0 += b.x; v1 += b.y; v2 += b.x; v3 += b.y;
            }
            if (HALF_OUT) {
                __half* Cb = (__half*)C + (long)blockIdx.z * sC;
                __half2 h0 = __floats2half2_rn(v0, v1);
                __half2 h1 = __floats2half2_rn(v2, v3);
                *(__half2*)&Cb[(long)row * N + col]       = h0;
                *(__half2*)&Cb[(long)(row + 8) * N + col] = h1;
            } else {
                float* Cb = (float*)C + (long)blockIdx.z * sC;
                *(float2*)&Cb[(long)row * N + col]       = make_float2(v0, v1);
                *(float2*)&Cb[(long)(row + 8) * N + col] = make_float2(v2, v3);
            }
        }
    }
}

// ---------------------------------------------------------------------------
// V transpose (fp16): [B][S][D] -> [B][D][S]
// ---------------------------------------------------------------------------
__global__ __launch_bounds__(256)
void transpose_h(const __half* __restrict__ in, __half* __restrict__ out)
{
    __shared__ __half t[32][34];
    const __half* ib = in  + (long)blockIdx.z * SEQ * DIM;
    __half*       ob = out + (long)blockIdx.z * DIM * SEQ;
    const int d0 = blockIdx.x * 32;
    const int s0 = blockIdx.y * 32;
    const int tx = threadIdx.x;       // 0..31
    const int ty = threadIdx.y;       // 0..7
    #pragma unroll
    for (int j = 0; j < 32; j += 8)
        t[ty + j][tx] = ib[(long)(s0 + ty + j) * DIM + d0 + tx];
    __syncthreads();
    #pragma unroll
    for (int j = 0; j < 32; j += 8)
        ob[(long)(d0 + ty + j) * SEQ + s0 + tx] = t[tx][ty + j];
}

// ---------------------------------------------------------------------------
// In-place row softmax (exact fp32 -> data) + fp16 copy -> ph
// ---------------------------------------------------------------------------
__global__ __launch_bounds__(256)
void softmax_kernel(float* __restrict__ data, __half* __restrict__ ph)
{
    constexpr int NC = SEQ;
    constexpr int PT = NC / 256;

    const long roff = (long)blockIdx.x * NC;
    float*  row = data + roff;
    __half* rh  = ph + roff;
    __shared__ float red[8];

    const int tid  = threadIdx.x;
    const int lane = tid & 31;
    const int warp = tid >> 5;

    float v[PT];
    #pragma unroll
    for (int i = 0; i < PT; ++i) v[i] = row[tid + i * 256];

    float lmax = v[0];
    #pragma unroll
    for (int i = 1; i < PT; ++i) lmax = fmaxf(lmax, v[i]);
    #pragma unroll
    for (int o = 16; o > 0; o >>= 1)
        lmax = fmaxf(lmax, __shfl_xor_sync(0xFFFFFFFFu, lmax, o));
    if (lane == 0) red[warp] = lmax;
    __syncthreads();
    float rmax = red[0];
    #pragma unroll
    for (int w = 1; w < 8; ++w) rmax = fmaxf(rmax, red[w]);
    __syncthreads();

    float lsum = 0.0f;
    #pragma unroll
    for (int i = 0; i < PT; ++i) {
        v[i] = __expf(v[i] - rmax);
        lsum += v[i];
    }
    #pragma unroll
    for (int o = 16; o > 0; o >>= 1)
        lsum += __shfl_xor_sync(0xFFFFFFFFu, lsum, o);
    if (lane == 0) red[warp] = lsum;
    __syncthreads();
    float rsum = 0.0f;
    #pragma unroll
    for (int w = 0; w < 8; ++w) rsum += red[w];

    const float inv = 1.0f / rsum;
    #pragma unroll
    for (int i = 0; i < PT; ++i) {
        const int idx = tid + i * 256;
        const float o = v[i] * inv;
        row[idx] = o;
        rh[idx]  = __float2half_rn(o);
    }
}

// ---------------------------------------------------------------------------
// Launch: cvt(x,W) -> QKV proj -> V^T -> scores -> softmax -> AV
// Output layout: [weighted_sum B*S*D | attention_weights B*S*S]
// ---------------------------------------------------------------------------
extern "C" void kernel_launch(void* const* d_in, const int* in_sizes, int n_in,
                              void* d_out, int out_size)
{
    const float* x  = (const float*)d_in[0];
    const float* Wq = (const float*)d_in[1];
    const float* bq = (const float*)d_in[2];
    const float* Wk = (const float*)d_in[3];
    const float* bk = (const float*)d_in[4];
    const float* Wv = (const float*)d_in[5];
    const float* bv = (const float*)d_in[6];

    float* out_ws = (float*)d_out;
    float* out_aw = (float*)d_out + (long)BATCH * SEQ * DIM;

    __half *xh, *wq, *wk, *wv, *q, *k, *v, *vt, *p;
    cudaGetSymbolAddress((void**)&xh, g_x);
    cudaGetSymbolAddress((void**)&wq, g_wq);
    cudaGetSymbolAddress((void**)&wk, g_wk);
    cudaGetSymbolAddress((void**)&wv, g_wv);
    cudaGetSymbolAddress((void**)&q,  g_q);
    cudaGetSymbolAddress((void**)&k,  g_k);
    cudaGetSymbolAddress((void**)&v,  g_v);
    cudaGetSymbolAddress((void**)&vt, g_vt);
    cudaGetSymbolAddress((void**)&p,  g_p);

    // smem: 2 stages x 2 tiles x 128 rows x 40 halves x 2B = 40960 B
    const int smem_sz = 2 * 2 * 128 * 40 * 2;
    cudaFuncSetAttribute(gemm_h<true >, cudaFuncAttributeMaxDynamicSharedMemorySize, smem_sz);
    cudaFuncSetAttribute(gemm_h<false>, cudaFuncAttributeMaxDynamicSharedMemorySize, smem_sz);

    const dim3 blk(256);

    // 0) convert inputs to fp16
    {
        const int nx = BATCH * SEQ * DIM / 4;
        const int nw = DIM * DIM / 4;
        cvt_half_kernel<<<(nx + 255) / 256, blk>>>(x,  xh, nx);
        cvt_half_kernel<<<(nw + 255) / 256, blk>>>(Wq, wq, nw);
        cvt_half_kernel<<<(nw + 255) / 256, blk>>>(Wk, wk, nw);
        cvt_half_kernel<<<(nw + 255) / 256, blk>>>(Wv, wv, nw);
    }

    // 1) QKV projections: [8192,1024] = xh @ W^T + b, fp16 outputs
    {
        dim3 grid(DIM / 128, (BATCH * SEQ) / 128, 1);
        gemm_h<true><<<grid, blk, smem_sz>>>(xh, wq, bq, q,
                                             BATCH * SEQ, DIM, DIM, 1.0f, 0, 0, 0);
        gemm_h<true><<<grid, blk, smem_sz>>>(xh, wk, bk, k,
                                             BATCH * SEQ, DIM, DIM, 1.0f, 0, 0, 0);
        gemm_h<true><<<grid, blk, smem_sz>>>(xh, wv, bv, v,
                                             BATCH * SEQ, DIM, DIM, 1.0f, 0, 0, 0);
    }

    // 2) V^T: [S,D] -> [D,S] fp16
    {
        dim3 tgrid(DIM / 32, SEQ / 32, BATCH);
        transpose_h<<<tgrid, dim3(32, 8)>>>(v, vt);
    }

    // 3) scores = (Q @ K^T) / 32, fp32 store into attention-weights region
    {
        dim3 grid(SEQ / 128, SEQ / 128, BATCH);
        gemm_h<false><<<grid, blk, smem_sz>>>(q, k, nullptr, out_aw,
                                              SEQ, SEQ, DIM, 0.03125f,
                                              (long)SEQ * DIM, (long)SEQ * DIM,
                                              (long)SEQ * SEQ);
    }

    // 4) softmax: exact fp32 -> out_aw, fp16 -> p
    softmax_kernel<<<BATCH * SEQ, blk>>>(out_aw, p);

    // 5) weighted_sum = P @ Vt^T  (Vt: [D,S] = B[N=D,K=S]), fp32 out
    {
        dim3 grid(DIM / 128, SEQ / 128, BATCH);
        gemm_h<false><<<grid, blk, smem_sz>>>(p, vt, nullptr, out_ws,
                                              SEQ, DIM, SEQ, 1.0f,
                                              (long)SEQ * SEQ, (long)DIM * SEQ,
                                              (long)SEQ * DIM);
    }
}